// round 13
// baseline (speedup 1.0000x reference)
#include <cuda_runtime.h>
#include <cstdint>

// ---------------------------------------------------------------------------
// TopK AutoEncoder: recon = (topk(A @ W_enc)) @ W_dec + b_pre
// Outputs (tuple order): recon [B,D], acts [B,H], z [B,H]
// B=4096, D=768, H=24576, k=32
// GEMM: mma.sync m16n8k16 bf16x3 (R10, traffic-pure).
// K2a: flat stream: read acts / write z=0 / collect candidates (> 0.55).
// K2b: per-row exact radix on candidates + fp64 band + scatter + decode.
// ---------------------------------------------------------------------------

#define NROWS 4096
#define GCAP 1024
#define TGLOB 0.55f

__device__ int   g_cnt[NROWS];
__device__ float g_cval[(size_t)NROWS * GCAP];
__device__ int   g_cidx[(size_t)NROWS * GCAP];

__global__ void zero_cnt_kernel() {
    int i = blockIdx.x * blockDim.x + threadIdx.x;
    if (i < NROWS) g_cnt[i] = 0;
}

__device__ __forceinline__ uint32_t bf16hi_bits(float x) {
    uint32_t u = __float_as_uint(x);
    return (u + 0x7FFFu + ((u >> 16) & 1u)) & 0xFFFF0000u;
}
__device__ __forceinline__ void split_pair(float x0, float x1,
                                           uint32_t& hi, uint32_t& lo) {
    uint32_t h0 = bf16hi_bits(x0), h1 = bf16hi_bits(x1);
    hi = __byte_perm(h0, h1, 0x7632);
    float l0 = x0 - __uint_as_float(h0);
    float l1 = x1 - __uint_as_float(h1);
    asm("cvt.rn.bf16x2.f32 %0, %1, %2;" : "=r"(lo) : "f"(l1), "f"(l0));
}
__device__ __forceinline__ void mma16(float* c, const uint32_t* a, const uint32_t* b) {
    asm volatile(
        "mma.sync.aligned.m16n8k16.row.col.f32.bf16.bf16.f32 "
        "{%0,%1,%2,%3}, {%4,%5,%6,%7}, {%8,%9}, {%0,%1,%2,%3};"
        : "+f"(c[0]), "+f"(c[1]), "+f"(c[2]), "+f"(c[3])
        : "r"(a[0]), "r"(a[1]), "r"(a[2]), "r"(a[3]), "r"(b[0]), "r"(b[1]));
}

// ===================== Kernel 1: encode GEMM (bf16x3, pure R10) =============
#define BM 128
#define BN 256
#define NCH 48
#define AP 12
#define WP 12
#define AS_W (128 * AP)
#define WS_W (256 * WP)
#define GEMM_SMEM ((4 * AS_W + 4 * WS_W) * 4)

__global__ void __launch_bounds__(256, 1)
encode_gemm_bf16(const float* __restrict__ A,
                 const float* __restrict__ W,
                 const float* __restrict__ bpre,
                 float* __restrict__ acts,
                 int D, int H)
{
    extern __shared__ uint32_t sm[];
    uint32_t* AhS[2] = { sm,            sm + 2 * AS_W };
    uint32_t* AlS[2] = { sm + AS_W,     sm + 3 * AS_W };
    uint32_t* WhS[2] = { sm + 4 * AS_W,            sm + 4 * AS_W + 2 * WS_W };
    uint32_t* WlS[2] = { sm + 4 * AS_W + WS_W,     sm + 4 * AS_W + 3 * WS_W };

    const int tid = threadIdx.x;
    const int w = tid >> 5;
    const int lane = tid & 31;
    const int lr = lane >> 2;
    const int lc = lane & 3;
    const int wm = w >> 2;
    const int wn = w & 3;
    const int m0 = blockIdx.x * BM;
    const int n0 = blockIdx.y * BN;

    float C[4][8][4];
#pragma unroll
    for (int mt = 0; mt < 4; mt++)
#pragma unroll
        for (int nt = 0; nt < 8; nt++)
#pragma unroll
            for (int r = 0; r < 4; r++) C[mt][nt][r] = 0.0f;

    float4 aw[2];
    float ww[16];

    {
#pragma unroll
        for (int i = 0; i < 2; i++) {
            int idx = tid + 256 * i;
            int m = idx >> 2, kq = (idx & 3) * 4;
            aw[i] = *(const float4*)(A + (size_t)(m0 + m) * D + kq);
        }
        const float* wp = W + n0 + tid;
#pragma unroll
        for (int r = 0; r < 16; r++) ww[r] = __ldg(wp + (size_t)r * H);
    }

#pragma unroll 1
    for (int c = 0; c < NCH; c++) {
        const int buf = c & 1;
        const int k0 = c * 16;
        const int k0n = k0 + 16;
        const bool more = (c + 1 < NCH);

        {
            uint32_t* Ah = AhS[buf];
            uint32_t* Al = AlS[buf];
#pragma unroll
            for (int i = 0; i < 2; i++) {
                int idx = tid + 256 * i;
                int m = idx >> 2, kq = (idx & 3) * 4;
                float4 av = aw[i];
                float4 bv = *(const float4*)(bpre + k0 + kq);
                uint32_t h0, l0, h1, l1;
                split_pair(av.x - bv.x, av.y - bv.y, h0, l0);
                split_pair(av.z - bv.z, av.w - bv.w, h1, l1);
                int j = kq >> 1;
                *(uint2*)&Ah[m * AP + j] = make_uint2(h0, h1);
                *(uint2*)&Al[m * AP + j] = make_uint2(l0, l1);
            }
            uint32_t ph[8], pl[8];
#pragma unroll
            for (int j = 0; j < 8; j++)
                split_pair(ww[2 * j], ww[2 * j + 1], ph[j], pl[j]);
            uint32_t* Wh = WhS[buf];
            uint32_t* Wl = WlS[buf];
            *(uint4*)&Wh[tid * WP + 0] = make_uint4(ph[0], ph[1], ph[2], ph[3]);
            *(uint4*)&Wh[tid * WP + 4] = make_uint4(ph[4], ph[5], ph[6], ph[7]);
            *(uint4*)&Wl[tid * WP + 0] = make_uint4(pl[0], pl[1], pl[2], pl[3]);
            *(uint4*)&Wl[tid * WP + 4] = make_uint4(pl[4], pl[5], pl[6], pl[7]);
        }
        __syncthreads();

        if (more) {
#pragma unroll
            for (int i = 0; i < 2; i++) {
                int idx = tid + 256 * i;
                int m = idx >> 2, kq = (idx & 3) * 4;
                aw[i] = *(const float4*)(A + (size_t)(m0 + m) * D + k0n + kq);
            }
            const float* wp = W + (size_t)k0n * H + n0 + tid;
#pragma unroll
            for (int r = 0; r < 16; r++) ww[r] = __ldg(wp + (size_t)r * H);
        }

        {
            const uint32_t* Ah = AhS[buf];
            const uint32_t* Al = AlS[buf];
            const uint32_t* Wh = WhS[buf];
            const uint32_t* Wl = WlS[buf];
            uint32_t Bh[8][2], Bl[8][2];
#pragma unroll
            for (int nt = 0; nt < 8; nt++) {
                int n = wn * 64 + nt * 8 + lr;
                Bh[nt][0] = Wh[n * WP + lc];
                Bh[nt][1] = Wh[n * WP + lc + 4];
                Bl[nt][0] = Wl[n * WP + lc];
                Bl[nt][1] = Wl[n * WP + lc + 4];
            }
#pragma unroll
            for (int mt = 0; mt < 4; mt++) {
                int m = wm * 64 + mt * 16 + lr;
                uint32_t Af[4]  = { Ah[m * AP + lc],      Ah[(m + 8) * AP + lc],
                                    Ah[m * AP + lc + 4],  Ah[(m + 8) * AP + lc + 4] };
                uint32_t Afl[4] = { Al[m * AP + lc],      Al[(m + 8) * AP + lc],
                                    Al[m * AP + lc + 4],  Al[(m + 8) * AP + lc + 4] };
#pragma unroll
                for (int nt = 0; nt < 8; nt++) mma16(C[mt][nt], Af, Bh[nt]);
#pragma unroll
                for (int nt = 0; nt < 8; nt++) mma16(C[mt][nt], Af, Bl[nt]);
#pragma unroll
                for (int nt = 0; nt < 8; nt++) mma16(C[mt][nt], Afl, Bh[nt]);
            }
        }
    }

#pragma unroll
    for (int mt = 0; mt < 4; mt++) {
        const int r0 = m0 + wm * 64 + mt * 16 + lr;
#pragma unroll
        for (int nt = 0; nt < 8; nt++) {
            const int cc = n0 + wn * 64 + nt * 8 + 2 * lc;
            *(float2*)(acts + (size_t)r0 * H + cc) =
                make_float2(C[mt][nt][0], C[mt][nt][1]);
            *(float2*)(acts + (size_t)(r0 + 8) * H + cc) =
                make_float2(C[mt][nt][2], C[mt][nt][3]);
        }
    }
}

// ===== Kernel 2a: flat stream: acts read, z=0 write, candidate collect ======
#define SEG 4096
#define STREAM_THREADS 256

__global__ void __launch_bounds__(STREAM_THREADS)
stream_kernel(const float* __restrict__ acts,
              float* __restrict__ z,
              int H)
{
    const int segs_per_row = H / SEG;
    const int row = blockIdx.x / segs_per_row;
    const int seg = blockIdx.x % segs_per_row;
    const size_t base = (size_t)row * H + (size_t)seg * SEG;
    const int tid = threadIdx.x;

    const float4 zf4 = make_float4(0.f, 0.f, 0.f, 0.f);
#pragma unroll
    for (int it = 0; it < SEG / (STREAM_THREADS * 4); it++) {
        const int off = (tid + it * STREAM_THREADS) * 4;
        float4 v = __ldcs((const float4*)(acts + base + off));
        __stcs((float4*)(z + base + off), zf4);
        const int j0 = seg * SEG + off;
#pragma unroll
        for (int t = 0; t < 4; t++) {
            float f = (t == 0) ? v.x : (t == 1) ? v.y : (t == 2) ? v.z : v.w;
            if (f > TGLOB) {
                int p = atomicAdd(&g_cnt[row], 1);
                if (p < GCAP) {
                    g_cval[(size_t)row * GCAP + p] = f;
                    g_cidx[(size_t)row * GCAP + p] = j0 + t;
                }
            }
        }
    }
}

// ======== Kernel 2b: candidate top-k + fp64 band + z scatter + decode =======
__device__ __forceinline__ unsigned int f2key(float f) {
    unsigned int u = __float_as_uint(f);
    return (u & 0x80000000u) ? ~u : (u | 0x80000000u);
}
__device__ __forceinline__ float key2f(unsigned int u) {
    unsigned int b = (u & 0x80000000u) ? (u ^ 0x80000000u) : ~u;
    return __uint_as_float(b);
}

#define TK_THREADS 256
#define CAND_CAP 3072
#define SEL_CAP 48
#define BAND_CAP 64
#define BAND_EPS 2e-3f

__global__ void __launch_bounds__(TK_THREADS)
topk_decode_kernel(const float* __restrict__ acts,
                   const float* __restrict__ A,
                   const float* __restrict__ Wenc,
                   const float* __restrict__ Wdec,
                   const float* __restrict__ bpre,
                   const int* __restrict__ kptr,
                   float* __restrict__ z,
                   float* __restrict__ recon,
                   int H, int D)
{
    __shared__ unsigned int hist[256];
    __shared__ unsigned int ck[CAND_CAP];
    __shared__ int          ci[CAND_CAP];
    __shared__ int nc, bq_sh;
    __shared__ unsigned int sh_prefix, sh_mask;
    __shared__ int sh_remaining;
    __shared__ int ncore, nband, ntot;
    __shared__ int   tki[SEL_CAP];
    __shared__ float tkv[SEL_CAP];
    __shared__ int    bidx[BAND_CAP];
    __shared__ float  bvalf[BAND_CAP];
    __shared__ double bvald[BAND_CAP];
    __shared__ unsigned char bsel[BAND_CAP];

    const int row = blockIdx.x;
    const int tid = threadIdx.x;
    const int lane = tid & 31;
    const int wid = tid >> 5;
    const int k = *kptr;
    const float* arow = acts + (size_t)row * H;
    float* zrow = z + (size_t)row * H;

    if (tid == 0) { ncore = 0; nband = 0; ntot = 0; nc = 0; }
    __syncthreads();

    // ---- phase 1: fetch candidates from side channel (fast path: cnt>=48)
    int gcnt = g_cnt[row];
    int n;
    if (gcnt >= SEL_CAP && gcnt <= GCAP) {
        for (int m = tid; m < gcnt; m += TK_THREADS) {
            ck[m] = f2key(g_cval[(size_t)row * GCAP + m]);
            ci[m] = g_cidx[(size_t)row * GCAP + m];
        }
        n = gcnt;
        __syncthreads();
    } else {
        // ---- fallback: sampled-threshold full-row rescan (statistically never)
        hist[tid] = 0u;
        __syncthreads();
        {
            const int stride = H / 512;
            unsigned int k0 = f2key(__ldg(arow + (size_t)tid * stride));
            unsigned int k1 = f2key(__ldg(arow + (size_t)(tid + 256) * stride));
            atomicAdd(&hist[k0 >> 24], 1u);
            atomicAdd(&hist[k1 >> 24], 1u);
        }
        __syncthreads();
        if (tid == 0) {
            int acc = 0, b = 255;
            for (; b >= 1; b--) { acc += (int)hist[b]; if (acc >= 10) break; }
            bq_sh = b; nc = 0;
        }
        __syncthreads();
        unsigned int Tkey = (unsigned int)bq_sh << 24;
        int guard = 0;
        for (;;) {
            for (int jq = tid; jq < H / 4; jq += TK_THREADS) {
                const int j = jq * 4;
                float4 v = *(const float4*)(arow + j);
                unsigned int kk[4] = { f2key(v.x), f2key(v.y), f2key(v.z), f2key(v.w) };
#pragma unroll
                for (int t = 0; t < 4; t++) {
                    if (kk[t] >= Tkey) {
                        int p = atomicAdd(&nc, 1);
                        if (p < CAND_CAP) { ck[p] = kk[t]; ci[p] = j + t; }
                    }
                }
            }
            __syncthreads();
            int nn = nc;
            if ((nn >= k && nn <= CAND_CAP) || guard >= 9) break;
            if (tid == 0) {
                bq_sh = (nn < k) ? max(bq_sh - 1, 0) : min(bq_sh + 1, 255);
                nc = 0;
            }
            __syncthreads();
            Tkey = (unsigned int)bq_sh << 24;
            guard++;
        }
        n = min(nc, CAND_CAP);
    }

    // ---- phase 2: exact radix select (k-th largest) among candidates
    if (tid == 0) { sh_prefix = 0u; sh_mask = 0u; sh_remaining = k; }
    __syncthreads();
#pragma unroll
    for (int shift = 24; shift >= 0; shift -= 8) {
        hist[tid] = 0u;
        __syncthreads();
        unsigned int pfx = sh_prefix, msk = sh_mask;
        for (int m = tid; m < n; m += TK_THREADS) {
            unsigned int u = ck[m];
            if ((u & msk) == pfx)
                atomicAdd(&hist[(u >> shift) & 255u], 1u);
        }
        __syncthreads();
        if (tid == 0) {
            int rem = sh_remaining;
            for (int b = 255; b >= 0; b--) {
                int c = (int)hist[b];
                if (c >= rem) {
                    sh_prefix |= ((unsigned int)b) << shift;
                    sh_mask   |= 0xFFu << shift;
                    sh_remaining = rem;
                    break;
                }
                rem -= c;
            }
        }
        __syncthreads();
    }
    const float v_t = key2f(sh_prefix);

    // ---- phase 3: classify candidates -> core / band
    for (int m = tid; m < n; m += TK_THREADS) {
        float f = key2f(ck[m]);
        if (f > v_t + BAND_EPS) {
            int p = atomicAdd(&ncore, 1);
            if (p < SEL_CAP) { tki[p] = ci[m]; tkv[p] = f; }
        } else if (fabsf(f - v_t) <= BAND_EPS) {
            int p = atomicAdd(&nband, 1);
            if (p < BAND_CAP) { bidx[p] = ci[m]; bvalf[p] = f; }
        }
    }
    __syncthreads();

    // ---- phase 4: fp64 re-evaluation of band members (one warp each)
    const int nb = min(nband, BAND_CAP);
    for (int m = wid; m < nb; m += TK_THREADS / 32) {
        int j = bidx[m];
        double acc = 0.0;
        for (int d = lane; d < D; d += 32)
            acc += (double)(A[(size_t)row * D + d] - bpre[d]) *
                   (double)Wenc[(size_t)d * H + j];
#pragma unroll
        for (int o = 16; o > 0; o >>= 1)
            acc += __shfl_down_sync(0xFFFFFFFFu, acc, o);
        if (lane == 0) bvald[m] = acc;
    }
    __syncthreads();

    if (tid == 0) {
        int base = min(ncore, SEL_CAP);
        int slots = k - base;
        if (slots < 0) slots = 0;
        if (slots > nb) slots = nb;
        for (int m = 0; m < nb; m++) bsel[m] = 0;
        for (int s = 0; s < slots; s++) {
            int best = -1;
            for (int m = 0; m < nb; m++) {
                if (bsel[m]) continue;
                if (best < 0 ||
                    bvald[m] > bvald[best] ||
                    (bvald[m] == bvald[best] && bidx[m] < bidx[best]))
                    best = m;
            }
            bsel[best] = 1;
            if (base + s < SEL_CAP) { tki[base + s] = bidx[best]; tkv[base + s] = bvalf[best]; }
        }
        int nt = min(base + slots, SEL_CAP);
        for (int i = 1; i < nt; i++) {
            int ii = tki[i]; float vv = tkv[i];
            int jx = i - 1;
            while (jx >= 0 && tki[jx] > ii) {
                tki[jx + 1] = tki[jx]; tkv[jx + 1] = tkv[jx]; jx--;
            }
            tki[jx + 1] = ii; tkv[jx + 1] = vv;
        }
        ntot = nt;
    }
    __syncthreads();

    // ---- phase 5: z scatter (z zeroed by stream kernel)
    const int ns = ntot;
    for (int i = tid; i < ns; i += TK_THREADS)
        zrow[tki[i]] = tkv[i];

    // ---- phase 6: sparse decode
    for (int d = tid; d < D; d += TK_THREADS) {
        float acc = bpre[d];
        for (int i = 0; i < ns; i++)
            acc = fmaf(tkv[i], Wdec[(size_t)tki[i] * D + d], acc);
        recon[(size_t)row * D + d] = acc;
    }
}

// ---------------------------------------------------------------------------

extern "C" void kernel_launch(void* const* d_in, const int* in_sizes, int n_in,
                              void* d_out, int out_size)
{
    const float* A    = (const float*)d_in[0];
    const float* Wenc = (const float*)d_in[1];
    const float* Wdec = (const float*)d_in[2];
    const float* bpre = (const float*)d_in[3];
    const int*   kptr = (const int*)d_in[4];

    const int D = in_sizes[3];            // 768
    const int B = in_sizes[0] / D;        // 4096
    const int H = in_sizes[1] / D;        // 24576

    float* out   = (float*)d_out;
    float* recon = out;                                   // [B, D]
    float* acts  = out + (size_t)B * D;                   // [B, H]
    float* z     = out + (size_t)B * D + (size_t)B * H;   // [B, H]

    static bool attr_set = false;
    if (!attr_set) {
        cudaFuncSetAttribute(encode_gemm_bf16,
                             cudaFuncAttributeMaxDynamicSharedMemorySize,
                             GEMM_SMEM);
        attr_set = true;
    }

    zero_cnt_kernel<<<(NROWS + 255) / 256, 256>>>();

    dim3 g1(B / BM, H / BN);
    encode_gemm_bf16<<<g1, 256, GEMM_SMEM>>>(A, Wenc, bpre, acts, D, H);

    stream_kernel<<<B * (H / SEG), STREAM_THREADS>>>(acts, z, H);

    topk_decode_kernel<<<B, TK_THREADS>>>(acts, A, Wenc, Wdec, bpre,
                                          kptr, z, recon, H, D);
}

// round 15
// speedup vs baseline: 1.0517x; 1.0517x over previous
#include <cuda_runtime.h>
#include <cstdint>

// ---------------------------------------------------------------------------
// TopK AutoEncoder: recon = (topk(A @ W_enc)) @ W_dec + b_pre
// Outputs (tuple order): recon [B,D], acts [B,H], z [B,H]
// B=4096, D=768, H=24576, k=32
// GEMM: mma.sync m16n8k16 bf16x3 (R10, traffic-pure).
// K2 (R14): one block/row, 512 thr: single streaming pass (ldcs acts, stcs z=0,
// fixed threshold 0.55 candidate collect) + exact radix + fp64 band + decode.
// ---------------------------------------------------------------------------

__device__ __forceinline__ uint32_t bf16hi_bits(float x) {
    uint32_t u = __float_as_uint(x);
    return (u + 0x7FFFu + ((u >> 16) & 1u)) & 0xFFFF0000u;
}
__device__ __forceinline__ void split_pair(float x0, float x1,
                                           uint32_t& hi, uint32_t& lo) {
    uint32_t h0 = bf16hi_bits(x0), h1 = bf16hi_bits(x1);
    hi = __byte_perm(h0, h1, 0x7632);
    float l0 = x0 - __uint_as_float(h0);
    float l1 = x1 - __uint_as_float(h1);
    asm("cvt.rn.bf16x2.f32 %0, %1, %2;" : "=r"(lo) : "f"(l1), "f"(l0));
}
__device__ __forceinline__ void mma16(float* c, const uint32_t* a, const uint32_t* b) {
    asm volatile(
        "mma.sync.aligned.m16n8k16.row.col.f32.bf16.bf16.f32 "
        "{%0,%1,%2,%3}, {%4,%5,%6,%7}, {%8,%9}, {%0,%1,%2,%3};"
        : "+f"(c[0]), "+f"(c[1]), "+f"(c[2]), "+f"(c[3])
        : "r"(a[0]), "r"(a[1]), "r"(a[2]), "r"(a[3]), "r"(b[0]), "r"(b[1]));
}

// ===================== Kernel 1: encode GEMM (bf16x3, pure R10) =============
#define BM 128
#define BN 256
#define NCH 48
#define AP 12
#define WP 12
#define AS_W (128 * AP)
#define WS_W (256 * WP)
#define GEMM_SMEM ((4 * AS_W + 4 * WS_W) * 4)

__global__ void __launch_bounds__(256, 1)
encode_gemm_bf16(const float* __restrict__ A,
                 const float* __restrict__ W,
                 const float* __restrict__ bpre,
                 float* __restrict__ acts,
                 int D, int H)
{
    extern __shared__ uint32_t sm[];
    uint32_t* AhS[2] = { sm,            sm + 2 * AS_W };
    uint32_t* AlS[2] = { sm + AS_W,     sm + 3 * AS_W };
    uint32_t* WhS[2] = { sm + 4 * AS_W,            sm + 4 * AS_W + 2 * WS_W };
    uint32_t* WlS[2] = { sm + 4 * AS_W + WS_W,     sm + 4 * AS_W + 3 * WS_W };

    const int tid = threadIdx.x;
    const int w = tid >> 5;
    const int lane = tid & 31;
    const int lr = lane >> 2;
    const int lc = lane & 3;
    const int wm = w >> 2;
    const int wn = w & 3;
    const int m0 = blockIdx.x * BM;
    const int n0 = blockIdx.y * BN;

    float C[4][8][4];
#pragma unroll
    for (int mt = 0; mt < 4; mt++)
#pragma unroll
        for (int nt = 0; nt < 8; nt++)
#pragma unroll
            for (int r = 0; r < 4; r++) C[mt][nt][r] = 0.0f;

    float4 aw[2];
    float ww[16];

    {
#pragma unroll
        for (int i = 0; i < 2; i++) {
            int idx = tid + 256 * i;
            int m = idx >> 2, kq = (idx & 3) * 4;
            aw[i] = *(const float4*)(A + (size_t)(m0 + m) * D + kq);
        }
        const float* wp = W + n0 + tid;
#pragma unroll
        for (int r = 0; r < 16; r++) ww[r] = __ldg(wp + (size_t)r * H);
    }

#pragma unroll 1
    for (int c = 0; c < NCH; c++) {
        const int buf = c & 1;
        const int k0 = c * 16;
        const int k0n = k0 + 16;
        const bool more = (c + 1 < NCH);

        {
            uint32_t* Ah = AhS[buf];
            uint32_t* Al = AlS[buf];
#pragma unroll
            for (int i = 0; i < 2; i++) {
                int idx = tid + 256 * i;
                int m = idx >> 2, kq = (idx & 3) * 4;
                float4 av = aw[i];
                float4 bv = *(const float4*)(bpre + k0 + kq);
                uint32_t h0, l0, h1, l1;
                split_pair(av.x - bv.x, av.y - bv.y, h0, l0);
                split_pair(av.z - bv.z, av.w - bv.w, h1, l1);
                int j = kq >> 1;
                *(uint2*)&Ah[m * AP + j] = make_uint2(h0, h1);
                *(uint2*)&Al[m * AP + j] = make_uint2(l0, l1);
            }
            uint32_t ph[8], pl[8];
#pragma unroll
            for (int j = 0; j < 8; j++)
                split_pair(ww[2 * j], ww[2 * j + 1], ph[j], pl[j]);
            uint32_t* Wh = WhS[buf];
            uint32_t* Wl = WlS[buf];
            *(uint4*)&Wh[tid * WP + 0] = make_uint4(ph[0], ph[1], ph[2], ph[3]);
            *(uint4*)&Wh[tid * WP + 4] = make_uint4(ph[4], ph[5], ph[6], ph[7]);
            *(uint4*)&Wl[tid * WP + 0] = make_uint4(pl[0], pl[1], pl[2], pl[3]);
            *(uint4*)&Wl[tid * WP + 4] = make_uint4(pl[4], pl[5], pl[6], pl[7]);
        }
        __syncthreads();

        if (more) {
#pragma unroll
            for (int i = 0; i < 2; i++) {
                int idx = tid + 256 * i;
                int m = idx >> 2, kq = (idx & 3) * 4;
                aw[i] = *(const float4*)(A + (size_t)(m0 + m) * D + k0n + kq);
            }
            const float* wp = W + (size_t)k0n * H + n0 + tid;
#pragma unroll
            for (int r = 0; r < 16; r++) ww[r] = __ldg(wp + (size_t)r * H);
        }

        {
            const uint32_t* Ah = AhS[buf];
            const uint32_t* Al = AlS[buf];
            const uint32_t* Wh = WhS[buf];
            const uint32_t* Wl = WlS[buf];
            uint32_t Bh[8][2], Bl[8][2];
#pragma unroll
            for (int nt = 0; nt < 8; nt++) {
                int n = wn * 64 + nt * 8 + lr;
                Bh[nt][0] = Wh[n * WP + lc];
                Bh[nt][1] = Wh[n * WP + lc + 4];
                Bl[nt][0] = Wl[n * WP + lc];
                Bl[nt][1] = Wl[n * WP + lc + 4];
            }
#pragma unroll
            for (int mt = 0; mt < 4; mt++) {
                int m = wm * 64 + mt * 16 + lr;
                uint32_t Af[4]  = { Ah[m * AP + lc],      Ah[(m + 8) * AP + lc],
                                    Ah[m * AP + lc + 4],  Ah[(m + 8) * AP + lc + 4] };
                uint32_t Afl[4] = { Al[m * AP + lc],      Al[(m + 8) * AP + lc],
                                    Al[m * AP + lc + 4],  Al[(m + 8) * AP + lc + 4] };
#pragma unroll
                for (int nt = 0; nt < 8; nt++) mma16(C[mt][nt], Af, Bh[nt]);
#pragma unroll
                for (int nt = 0; nt < 8; nt++) mma16(C[mt][nt], Af, Bl[nt]);
#pragma unroll
                for (int nt = 0; nt < 8; nt++) mma16(C[mt][nt], Afl, Bh[nt]);
            }
        }
    }

#pragma unroll
    for (int mt = 0; mt < 4; mt++) {
        const int r0 = m0 + wm * 64 + mt * 16 + lr;
#pragma unroll
        for (int nt = 0; nt < 8; nt++) {
            const int cc = n0 + wn * 64 + nt * 8 + 2 * lc;
            *(float2*)(acts + (size_t)r0 * H + cc) =
                make_float2(C[mt][nt][0], C[mt][nt][1]);
            *(float2*)(acts + (size_t)(r0 + 8) * H + cc) =
                make_float2(C[mt][nt][2], C[mt][nt][3]);
        }
    }
}

// ===== Kernel 2: single-pass stream + select + band + scatter + decode ======
__device__ __forceinline__ unsigned int f2key(float f) {
    unsigned int u = __float_as_uint(f);
    return (u & 0x80000000u) ? ~u : (u | 0x80000000u);
}
__device__ __forceinline__ float key2f(unsigned int u) {
    unsigned int b = (u & 0x80000000u) ? (u ^ 0x80000000u) : ~u;
    return __uint_as_float(b);
}

#define TK_THREADS 512
#define CAND_CAP 3072
#define SEL_CAP 48
#define BAND_CAP 64
#define BAND_EPS 2e-3f
#define TGLOB 0.55f

__global__ void __launch_bounds__(TK_THREADS)
topk_decode_kernel(const float* __restrict__ acts,
                   const float* __restrict__ A,
                   const float* __restrict__ Wenc,
                   const float* __restrict__ Wdec,
                   const float* __restrict__ bpre,
                   const int* __restrict__ kptr,
                   float* __restrict__ z,
                   float* __restrict__ recon,
                   int H, int D)
{
    __shared__ unsigned int hist[256];
    __shared__ unsigned int ck[CAND_CAP];
    __shared__ int          ci[CAND_CAP];
    __shared__ int nc;
    __shared__ float sh_T;
    __shared__ unsigned int sh_prefix, sh_mask;
    __shared__ int sh_remaining;
    __shared__ int ncore, nband, ntot;
    __shared__ int   tki[SEL_CAP];
    __shared__ float tkv[SEL_CAP];
    __shared__ int    bidx[BAND_CAP];
    __shared__ float  bvalf[BAND_CAP];
    __shared__ double bvald[BAND_CAP];
    __shared__ unsigned char bsel[BAND_CAP];

    const int row = blockIdx.x;
    const int tid = threadIdx.x;
    const int lane = tid & 31;
    const int wid = tid >> 5;
    const int k = *kptr;
    const float* arow = acts + (size_t)row * H;
    float* zrow = z + (size_t)row * H;

    if (tid == 0) {
        nc = 0; sh_T = TGLOB;
        ncore = 0; nband = 0; ntot = 0;
    }
    __syncthreads();

    // ---- phase 1: single streaming pass: read acts, write z=0, collect cands
    float T = sh_T;
    int guard = 0;
    const float4 zf4 = make_float4(0.f, 0.f, 0.f, 0.f);
    for (;;) {
        const bool first = (guard == 0);
#pragma unroll 4
        for (int jq = tid; jq < H / 4; jq += TK_THREADS) {
            const int j = jq * 4;
            float4 v = __ldcs((const float4*)(arow + j));
            if (first) __stcs((float4*)(zrow + j), zf4);
#pragma unroll
            for (int t = 0; t < 4; t++) {
                float f = (t == 0) ? v.x : (t == 1) ? v.y : (t == 2) ? v.z : v.w;
                if (f > T) {
                    int p = atomicAdd(&nc, 1);
                    if (p < CAND_CAP) { ck[p] = f2key(f); ci[p] = j + t; }
                }
            }
        }
        __syncthreads();
        int n = nc;
        if ((n >= k && n <= CAND_CAP) || guard >= 8) break;
        if (tid == 0) {
            sh_T = (n < k) ? (sh_T - 0.15f) : (sh_T + 0.15f);
            nc = 0;
        }
        __syncthreads();
        T = sh_T;
        guard++;
    }
    const int n = min(nc, CAND_CAP);

    // ---- phase 2: exact radix select (k-th largest) among candidates
    if (tid == 0) { sh_prefix = 0u; sh_mask = 0u; sh_remaining = k; }
    for (int i = tid; i < 256; i += TK_THREADS) hist[i] = 0u;
    __syncthreads();
#pragma unroll
    for (int shift = 24; shift >= 0; shift -= 8) {
        unsigned int pfx = sh_prefix, msk = sh_mask;
        for (int m = tid; m < n; m += TK_THREADS) {
            unsigned int u = ck[m];
            if ((u & msk) == pfx)
                atomicAdd(&hist[(u >> shift) & 255u], 1u);
        }
        __syncthreads();
        if (tid == 0) {
            int rem = sh_remaining;
            for (int b = 255; b >= 0; b--) {
                int c = (int)hist[b];
                if (c >= rem) {
                    sh_prefix |= ((unsigned int)b) << shift;
                    sh_mask   |= 0xFFu << shift;
                    sh_remaining = rem;
                    break;
                }
                rem -= c;
            }
        }
        __syncthreads();
        for (int i = tid; i < 256; i += TK_THREADS) hist[i] = 0u;
        __syncthreads();
    }
    const float v_t = key2f(sh_prefix);

    // ---- phase 3: classify candidates -> core / band
    for (int m = tid; m < n; m += TK_THREADS) {
        float f = key2f(ck[m]);
        if (f > v_t + BAND_EPS) {
            int p = atomicAdd(&ncore, 1);
            if (p < SEL_CAP) { tki[p] = ci[m]; tkv[p] = f; }
        } else if (fabsf(f - v_t) <= BAND_EPS) {
            int p = atomicAdd(&nband, 1);
            if (p < BAND_CAP) { bidx[p] = ci[m]; bvalf[p] = f; }
        }
    }
    __syncthreads();

    // ---- phase 4: fp64 re-evaluation of band members (one warp each)
    const int nb = min(nband, BAND_CAP);
    for (int m = wid; m < nb; m += TK_THREADS / 32) {
        int j = bidx[m];
        double acc = 0.0;
        for (int d = lane; d < D; d += 32)
            acc += (double)(A[(size_t)row * D + d] - bpre[d]) *
                   (double)Wenc[(size_t)d * H + j];
#pragma unroll
        for (int o = 16; o > 0; o >>= 1)
            acc += __shfl_down_sync(0xFFFFFFFFu, acc, o);
        if (lane == 0) bvald[m] = acc;
    }
    __syncthreads();

    if (tid == 0) {
        int base = min(ncore, SEL_CAP);
        int slots = k - base;
        if (slots < 0) slots = 0;
        if (slots > nb) slots = nb;
        for (int m = 0; m < nb; m++) bsel[m] = 0;
        for (int s = 0; s < slots; s++) {
            int best = -1;
            for (int m = 0; m < nb; m++) {
                if (bsel[m]) continue;
                if (best < 0 ||
                    bvald[m] > bvald[best] ||
                    (bvald[m] == bvald[best] && bidx[m] < bidx[best]))
                    best = m;
            }
            bsel[best] = 1;
            if (base + s < SEL_CAP) { tki[base + s] = bidx[best]; tkv[base + s] = bvalf[best]; }
        }
        int nt = min(base + slots, SEL_CAP);
        for (int i = 1; i < nt; i++) {
            int ii = tki[i]; float vv = tkv[i];
            int jx = i - 1;
            while (jx >= 0 && tki[jx] > ii) {
                tki[jx + 1] = tki[jx]; tkv[jx + 1] = tkv[jx]; jx--;
            }
            tki[jx + 1] = ii; tkv[jx + 1] = vv;
        }
        ntot = nt;
    }
    __syncthreads();

    // ---- phase 5: z scatter
    const int ns = ntot;
    for (int i = tid; i < ns; i += TK_THREADS)
        zrow[tki[i]] = tkv[i];

    // ---- phase 6: sparse decode (two d per thread max; MLP via 4 partials)
    for (int d = tid; d < D; d += TK_THREADS) {
        float a0 = bpre[d], a1 = 0.f, a2 = 0.f, a3 = 0.f;
        int i = 0;
        for (; i + 4 <= ns; i += 4) {
            a0 = fmaf(tkv[i + 0], __ldg(Wdec + (size_t)tki[i + 0] * D + d), a0);
            a1 = fmaf(tkv[i + 1], __ldg(Wdec + (size_t)tki[i + 1] * D + d), a1);
            a2 = fmaf(tkv[i + 2], __ldg(Wdec + (size_t)tki[i + 2] * D + d), a2);
            a3 = fmaf(tkv[i + 3], __ldg(Wdec + (size_t)tki[i + 3] * D + d), a3);
        }
        for (; i < ns; i++)
            a0 = fmaf(tkv[i], __ldg(Wdec + (size_t)tki[i] * D + d), a0);
        recon[(size_t)row * D + d] = ((a0 + a1) + (a2 + a3));
    }
}

// ---------------------------------------------------------------------------

extern "C" void kernel_launch(void* const* d_in, const int* in_sizes, int n_in,
                              void* d_out, int out_size)
{
    const float* A    = (const float*)d_in[0];
    const float* Wenc = (const float*)d_in[1];
    const float* Wdec = (const float*)d_in[2];
    const float* bpre = (const float*)d_in[3];
    const int*   kptr = (const int*)d_in[4];

    const int D = in_sizes[3];            // 768
    const int B = in_sizes[0] / D;        // 4096
    const int H = in_sizes[1] / D;        // 24576

    float* out   = (float*)d_out;
    float* recon = out;                                   // [B, D]
    float* acts  = out + (size_t)B * D;                   // [B, H]
    float* z     = out + (size_t)B * D + (size_t)B * H;   // [B, H]

    static bool attr_set = false;
    if (!attr_set) {
        cudaFuncSetAttribute(encode_gemm_bf16,
                             cudaFuncAttributeMaxDynamicSharedMemorySize,
                             GEMM_SMEM);
        attr_set = true;
    }

    dim3 g1(B / BM, H / BN);
    encode_gemm_bf16<<<g1, 256, GEMM_SMEM>>>(A, Wenc, bpre, acts, D, H);

    topk_decode_kernel<<<B, TK_THREADS>>>(acts, A, Wenc, Wdec, bpre,
                                          kptr, z, recon, H, D);
}